// round 9
// baseline (speedup 1.0000x reference)
#include <cuda_runtime.h>
#include <cuda_bf16.h>

#define B_ 2048
#define S_ 277
#define R_ 80
#define L_ 12
#define Z_ 56
#define NROWS (B_ * S_)          // 567296, divisible by 16
#define NBATCH (NROWS / 8)       // 70912
#define CHUNK 2
#define NCHUNK (NBATCH / CHUNK)  // 35456 exactly
#define VBLOCKS 64
#define VCHUNK (B_ / VBLOCKS)    // 32
#define TPB 256
#define WPB (TPB / 32)
#define FULL 0xffffffffu
#define R4 (R_ / 4)              // 20 float4 per row

__device__ double g_bce;
__device__ float  g_var[Z_ * Z_];
__device__ float  g_avg[Z_];
__device__ unsigned g_ticket;
__device__ unsigned g_work;

__global__ void __launch_bounds__(TPB, 4) mega_kernel(
    const float* __restrict__ x,
    const float* __restrict__ rx,
    const float* __restrict__ mu,
    const float* __restrict__ masks,
    const int*   __restrict__ lhs,
    float* __restrict__ out)
{
    __shared__ float  smem_buf[VCHUNK * Z_];      // var tile / final reduce
    __shared__ float4 smask4[L_ * R4];
    __shared__ int    slhs[R_];
    __shared__ float  swacc[WPB];
    __shared__ bool   s_last;

    const int tid = threadIdx.x;
    const int bid = blockIdx.x;

    {
        const float4* m4 = (const float4*)masks;
        for (int i = tid; i < L_ * R4; i += TPB) smask4[i] = m4[i];
        if (tid < R_) slhs[tid] = lhs[tid];
    }
    __syncthreads();

    // ---------------- var path: first VBLOCKS blocks do mu^T mu tile ------
    // (their late BCE start is absorbed by work stealing below)
    if (bid < VBLOCKS) {
        const int b0 = bid * VCHUNK;
        for (int i = tid; i < VCHUNK * Z_; i += TPB)
            smem_buf[i] = mu[(size_t)b0 * Z_ + i];
        __syncthreads();
        if (tid < Z_) {
            float s = 0.f;
            #pragma unroll
            for (int b = 0; b < VCHUNK; b++) s += smem_buf[b * Z_ + tid];
            atomicAdd(&g_avg[tid], s);
        }
        for (int p = tid; p < Z_ * Z_; p += TPB) {
            const int i = p / Z_, j = p % Z_;
            float s = 0.f;
            #pragma unroll
            for (int b = 0; b < VCHUNK; b++)
                s += smem_buf[b * Z_ + i] * smem_buf[b * Z_ + j];
            atomicAdd(&g_var[p], s);
        }
    }

    // ---------------- bce: warp-level work stealing, 8 rows per batch ------
    const int lane = tid & 31;
    const int warp = tid >> 5;
    const int sr   = lane >> 2;          // sub-row 0..7
    const int g    = lane & 3;           // chunk  0..3
    const int cbase = sr * R4 + g;       // float4 index within 8-row batch

    float acc = 0.f;

    unsigned cur = 0;
    if (lane == 0) cur = atomicAdd(&g_work, 1u);
    cur = __shfl_sync(FULL, cur, 0);

    while (cur < NCHUNK) {
        unsigned nxt = 0;                          // prefetch next chunk id:
        if (lane == 0) nxt = atomicAdd(&g_work, 1u); // latency hides under work

        #pragma unroll
        for (int i = 0; i < CHUNK; i++) {
            const size_t rowbase = ((size_t)cur * CHUNK + i) * 8;
            const float4* xb = (const float4*)(x  + rowbase * R_);
            const float4* rb = (const float4*)(rx + rowbase * R_);

            // front-batched loads: 10 independent LDG.128 in flight
            float4 xv[5], rv[5];
            #pragma unroll
            for (int k = 0; k < 5; k++) xv[k] = __ldcs(xb + cbase + 4 * k);
            #pragma unroll
            for (int k = 0; k < 5; k++) rv[k] = __ldcs(rb + cbase + 4 * k);

            // true index (trp) and p_true (rtp), 2 accumulators each
            float tr0 = 0.f, tr1 = 0.f, rt0 = 0.f, rt1 = 0.f;
            #pragma unroll
            for (int k = 0; k < 5; k++) {
                const float i0 = (float)(4 * g + 16 * k);
                tr0 = fmaf(xv[k].x, i0,       tr0);
                tr1 = fmaf(xv[k].y, i0 + 1.f, tr1);
                tr0 = fmaf(xv[k].z, i0 + 2.f, tr0);
                tr1 = fmaf(xv[k].w, i0 + 3.f, tr1);
                rt0 = fmaf(xv[k].x, rv[k].x, rt0);
                rt1 = fmaf(xv[k].y, rv[k].y, rt1);
                rt0 = fmaf(xv[k].z, rv[k].z, rt0);
                rt1 = fmaf(xv[k].w, rv[k].w, rt1);
            }
            float trp = tr0 + tr1, rtp = rt0 + rt1;
            trp += __shfl_xor_sync(FULL, trp, 1);
            rtp += __shfl_xor_sync(FULL, rtp, 1);
            trp += __shfl_xor_sync(FULL, trp, 2);
            rtp += __shfl_xor_sync(FULL, rtp, 2);

            const int lrow = slhs[__float2int_rn(trp)];

            // p = r*mask in place; row sum
            float s0 = 0.f, s1 = 0.f;
            #pragma unroll
            for (int k = 0; k < 5; k++) {
                const float4 m = smask4[lrow * R4 + g + 4 * k];
                rv[k].x *= m.x;  rv[k].y *= m.y;
                rv[k].z *= m.z;  rv[k].w *= m.w;
                s0 += rv[k].x + rv[k].y;
                s1 += rv[k].z + rv[k].w;
            }
            float s = s0 + s1;
            s += __shfl_xor_sync(FULL, s, 1);
            s += __shfl_xor_sync(FULL, s, 2);
            const float inv = __fdividef(1.0f, s);

            // product of (1 - o_r) over ALL r; true factor divided out below
            float pa = 1.f, pb = 1.f;
            #pragma unroll
            for (int k = 0; k < 5; k++) {
                pa *= fmaf(-rv[k].x, inv, 1.f) * fmaf(-rv[k].y, inv, 1.f);
                pb *= fmaf(-rv[k].z, inv, 1.f) * fmaf(-rv[k].w, inv, 1.f);
            }
            float pr = pa * pb;
            pr *= __shfl_xor_sync(FULL, pr, 1);
            pr *= __shfl_xor_sync(FULL, pr, 2);

            // log(o_true) + sum_{r != true} log(1-o_r)
            const float ot  = rtp * inv;
            const float omt = fmaf(-rtp, inv, 1.f);
            acc += __logf(__fdividef(ot * pr, omt));
        }

        nxt = __shfl_sync(FULL, nxt, 0);
        cur = nxt;
    }

    acc *= 0.25f;                          // each row counted by 4 lanes
    #pragma unroll
    for (int o = 16; o; o >>= 1) acc += __shfl_xor_sync(FULL, acc, o);
    if (lane == 0) swacc[warp] = acc;
    __syncthreads();
    if (tid == 0) {
        float t = 0.f;
        #pragma unroll
        for (int w2 = 0; w2 < WPB; w2++) t += swacc[w2];
        atomicAdd(&g_bce, (double)t);
    }

    // ---------------- ticket + last-block finalize -------------------------
    __threadfence();
    __syncthreads();
    if (tid == 0) {
        const unsigned t = atomicAdd(&g_ticket, 1u);
        s_last = (t == gridDim.x - 1);
    }
    __syncthreads();
    if (!s_last) return;
    __threadfence();

    float contrib = 0.f;
    for (int p = tid; p < Z_ * Z_; p += TPB) {
        const float v = fmaf(g_var[p], 1.0f / B_,
                             ((p / Z_) == (p % Z_)) ? -1.0f : 0.0f);
        contrib += fabsf(v);
        g_var[p] = 0.f;                          // reset for graph replay
    }
    contrib *= 1.0f / ((float)Z_ * (float)Z_);
    if (tid < Z_) {
        const float m = g_avg[tid] * (1.0f / B_);
        contrib += m * m * (1.0f / Z_);
        g_avg[tid] = 0.f;
    }
    smem_buf[tid] = contrib;
    __syncthreads();
    for (int o = TPB / 2; o; o >>= 1) {
        if (tid < o) smem_buf[tid] += smem_buf[tid + o];
        __syncthreads();
    }
    if (tid == 0) {
        const double bce = -g_bce / ((double)S_ * (double)B_);
        out[0] = (float)(bce + (double)smem_buf[0]);
        g_bce = 0.0;
        g_ticket = 0u;
        g_work = 0u;                             // reset work queue for replay
    }
}

extern "C" void kernel_launch(void* const* d_in, const int* in_sizes, int n_in,
                              void* d_out, int out_size) {
    const float* x     = (const float*)d_in[0];
    const float* rx    = (const float*)d_in[1];
    const float* mu    = (const float*)d_in[2];
    // d_in[3] = log_var (unused by the reference)
    const float* masks = (const float*)d_in[4];
    const int*   lhs   = (const int*)d_in[5];
    float* out = (float*)d_out;

    int dev = 0;
    cudaGetDevice(&dev);
    int sms = 148;
    cudaDeviceGetAttribute(&sms, cudaDevAttrMultiProcessorCount, dev);
    int nb = 0;
    cudaOccupancyMaxActiveBlocksPerMultiprocessor(&nb, mega_kernel, TPB, 0);
    if (nb < 1) nb = 1;
    int grid = sms * nb;                 // one resident wave
    if (grid < VBLOCKS + 1) grid = VBLOCKS + 1;

    mega_kernel<<<grid, TPB>>>(x, rx, mu, masks, lhs, out);
}

// round 10
// speedup vs baseline: 1.0931x; 1.0931x over previous
#include <cuda_runtime.h>
#include <cuda_bf16.h>

#define B_ 2048
#define S_ 277
#define R_ 80
#define L_ 12
#define Z_ 56
#define NROWS (B_ * S_)          // 567296
#define NBATCH (NROWS / 8)       // 70912
#define NV 64                    // var blocks (placed at grid tail)
#define VCHUNK (B_ / NV)         // 32
#define HANDICAP 4               // batches offloaded from each var block
#define TPB 256
#define WPB (TPB / 32)
#define FULL 0xffffffffu
#define R4 (R_ / 4)              // 20 float4 per row

__device__ double g_bce;
__device__ float  g_var[Z_ * Z_];
__device__ float  g_avg[Z_];
__device__ unsigned g_ticket;

__global__ void __launch_bounds__(TPB, 4) mega_kernel(
    const float* __restrict__ x,
    const float* __restrict__ rx,
    const float* __restrict__ mu,
    const float* __restrict__ masks,
    const int*   __restrict__ lhs,
    float* __restrict__ out)
{
    __shared__ float  smem_buf[VCHUNK * Z_];      // var tile / final reduce
    __shared__ float4 smask4[L_ * R4];
    __shared__ int    slhs[R_];
    __shared__ float  swacc[WPB];
    __shared__ unsigned s_qhead;
    __shared__ bool   s_last;

    const int tid = threadIdx.x;
    const int bid = blockIdx.x;
    const int G   = gridDim.x;

    {
        const float4* m4 = (const float4*)masks;
        for (int i = tid; i < L_ * R4; i += TPB) smask4[i] = m4[i];
        if (tid < R_) slhs[tid] = lhs[tid];
        if (tid == 0) s_qhead = 0u;
    }
    __syncthreads();

    // -------- per-block batch range (var blocks last, handicapped) --------
    const int nreg   = G - NV;
    const int cntv   = NBATCH / G - HANDICAP;
    const int remain = NBATCH - NV * cntv;
    const int cr     = remain / nreg;
    const int rem    = remain % nreg;
    int lo, cnt;
    if (bid < nreg) {
        cnt = cr + (bid < rem ? 1 : 0);
        lo  = bid * cr + (bid < rem ? bid : rem);
    } else {
        cnt = cntv;
        lo  = remain + (bid - nreg) * cntv;
    }

    // ---------------- var path: last NV blocks do mu^T mu tile ------------
    if (bid >= nreg) {
        const int b0 = (bid - nreg) * VCHUNK;
        for (int i = tid; i < VCHUNK * Z_; i += TPB)
            smem_buf[i] = mu[(size_t)b0 * Z_ + i];
        __syncthreads();
        if (tid < Z_) {
            float s = 0.f;
            #pragma unroll
            for (int b = 0; b < VCHUNK; b++) s += smem_buf[b * Z_ + tid];
            atomicAdd(&g_avg[tid], s);
        }
        for (int p = tid; p < Z_ * Z_; p += TPB) {
            const int i = p / Z_, j = p % Z_;
            float s = 0.f;
            #pragma unroll
            for (int b = 0; b < VCHUNK; b++)
                s += smem_buf[b * Z_ + i] * smem_buf[b * Z_ + j];
            atomicAdd(&g_var[p], s);
        }
    }

    // ---------------- bce: smem work queue, 8 rows per batch ---------------
    const int lane = tid & 31;
    const int warp = tid >> 5;
    const int sr   = lane >> 2;          // sub-row 0..7
    const int g    = lane & 3;           // float4 group 0..3
    const int cbase = sr * R4 + g;

    float acc = 0.f;

    unsigned cur = 0;
    if (lane == 0) cur = atomicAdd(&s_qhead, 1u);
    cur = __shfl_sync(FULL, cur, 0);

    while (cur < (unsigned)cnt) {
        unsigned nxt = 0;                 // prefetch next id (ATOMS ~30cy,
        if (lane == 0) nxt = atomicAdd(&s_qhead, 1u);  // hidden under work)

        const size_t rowbase = (size_t)(lo + (int)cur) * 8;
        const float4* xb = (const float4*)(x  + rowbase * R_);
        const float4* rb = (const float4*)(rx + rowbase * R_);

        // front-batched loads: 10 independent LDG.128 in flight
        float4 xv[5], rv[5];
        #pragma unroll
        for (int k = 0; k < 5; k++) xv[k] = __ldcs(xb + cbase + 4 * k);
        #pragma unroll
        for (int k = 0; k < 5; k++) rv[k] = __ldcs(rb + cbase + 4 * k);

        // true index (trp) and p_true (rtp), 2 accumulators each
        float tr0 = 0.f, tr1 = 0.f, rt0 = 0.f, rt1 = 0.f;
        #pragma unroll
        for (int k = 0; k < 5; k++) {
            const float i0 = (float)(4 * g + 16 * k);
            tr0 = fmaf(xv[k].x, i0,       tr0);
            tr1 = fmaf(xv[k].y, i0 + 1.f, tr1);
            tr0 = fmaf(xv[k].z, i0 + 2.f, tr0);
            tr1 = fmaf(xv[k].w, i0 + 3.f, tr1);
            rt0 = fmaf(xv[k].x, rv[k].x, rt0);
            rt1 = fmaf(xv[k].y, rv[k].y, rt1);
            rt0 = fmaf(xv[k].z, rv[k].z, rt0);
            rt1 = fmaf(xv[k].w, rv[k].w, rt1);
        }
        float trp = tr0 + tr1, rtp = rt0 + rt1;
        trp += __shfl_xor_sync(FULL, trp, 1);
        rtp += __shfl_xor_sync(FULL, rtp, 1);
        trp += __shfl_xor_sync(FULL, trp, 2);
        rtp += __shfl_xor_sync(FULL, rtp, 2);

        const int lrow = slhs[__float2int_rn(trp)];

        // p = r*mask in place; row sum
        float s0 = 0.f, s1 = 0.f;
        #pragma unroll
        for (int k = 0; k < 5; k++) {
            const float4 m = smask4[lrow * R4 + g + 4 * k];
            rv[k].x *= m.x;  rv[k].y *= m.y;
            rv[k].z *= m.z;  rv[k].w *= m.w;
            s0 += rv[k].x + rv[k].y;
            s1 += rv[k].z + rv[k].w;
        }
        float s = s0 + s1;
        s += __shfl_xor_sync(FULL, s, 1);
        s += __shfl_xor_sync(FULL, s, 2);
        const float inv = __fdividef(1.0f, s);

        // product of (1 - o_r) over ALL r; true factor divided out below
        float pa = 1.f, pb = 1.f;
        #pragma unroll
        for (int k = 0; k < 5; k++) {
            pa *= fmaf(-rv[k].x, inv, 1.f) * fmaf(-rv[k].y, inv, 1.f);
            pb *= fmaf(-rv[k].z, inv, 1.f) * fmaf(-rv[k].w, inv, 1.f);
        }
        float pr = pa * pb;
        pr *= __shfl_xor_sync(FULL, pr, 1);
        pr *= __shfl_xor_sync(FULL, pr, 2);

        // log(o_true) + sum_{r != true} log(1-o_r)
        const float ot  = rtp * inv;
        const float omt = fmaf(-rtp, inv, 1.f);
        acc += __logf(__fdividef(ot * pr, omt));

        nxt = __shfl_sync(FULL, nxt, 0);
        cur = nxt;
    }

    acc *= 0.25f;                          // each row counted by 4 lanes
    #pragma unroll
    for (int o = 16; o; o >>= 1) acc += __shfl_xor_sync(FULL, acc, o);
    if (lane == 0) swacc[warp] = acc;
    __syncthreads();
    if (tid == 0) {
        float t = 0.f;
        #pragma unroll
        for (int w2 = 0; w2 < WPB; w2++) t += swacc[w2];
        atomicAdd(&g_bce, (double)t);
    }

    // ---------------- ticket + last-block finalize -------------------------
    __threadfence();
    __syncthreads();
    if (tid == 0) {
        const unsigned t = atomicAdd(&g_ticket, 1u);
        s_last = (t == (unsigned)(G - 1));
    }
    __syncthreads();
    if (!s_last) return;
    __threadfence();

    float contrib = 0.f;
    for (int p = tid; p < Z_ * Z_; p += TPB) {
        const float v = fmaf(g_var[p], 1.0f / B_,
                             ((p / Z_) == (p % Z_)) ? -1.0f : 0.0f);
        contrib += fabsf(v);
        g_var[p] = 0.f;                          // reset for graph replay
    }
    contrib *= 1.0f / ((float)Z_ * (float)Z_);
    if (tid < Z_) {
        const float m = g_avg[tid] * (1.0f / B_);
        contrib += m * m * (1.0f / Z_);
        g_avg[tid] = 0.f;
    }
    smem_buf[tid] = contrib;
    __syncthreads();
    for (int o = TPB / 2; o; o >>= 1) {
        if (tid < o) smem_buf[tid] += smem_buf[tid + o];
        __syncthreads();
    }
    if (tid == 0) {
        const double bce = -g_bce / ((double)S_ * (double)B_);
        out[0] = (float)(bce + (double)smem_buf[0]);
        g_bce = 0.0;
        g_ticket = 0u;
    }
}

extern "C" void kernel_launch(void* const* d_in, const int* in_sizes, int n_in,
                              void* d_out, int out_size) {
    const float* x     = (const float*)d_in[0];
    const float* rx    = (const float*)d_in[1];
    const float* mu    = (const float*)d_in[2];
    // d_in[3] = log_var (unused by the reference)
    const float* masks = (const float*)d_in[4];
    const int*   lhs   = (const int*)d_in[5];
    float* out = (float*)d_out;

    int dev = 0;
    cudaGetDevice(&dev);
    int sms = 148;
    cudaDeviceGetAttribute(&sms, cudaDevAttrMultiProcessorCount, dev);
    int nb = 0;
    cudaOccupancyMaxActiveBlocksPerMultiprocessor(&nb, mega_kernel, TPB, 0);
    if (nb < 1) nb = 1;
    int grid = sms * nb;                 // one resident wave
    if (grid < NV + 8) grid = NV + 8;    // need nreg > 0 with sane split

    mega_kernel<<<grid, TPB>>>(x, rx, mu, masks, lhs, out);
}